// round 12
// baseline (speedup 1.0000x reference)
#include <cuda_runtime.h>
#include <float.h>
#include <math.h>

// Problem constants
constexpr int B  = 4;
constexpr int C  = 64;
constexpr int F  = 128;
constexpr int T  = 512;
constexpr int DC = 32;            // d_c
constexpr int THREADS = 1024;     // (t2 in [0,256)) x (h in [0,4))
constexpr int QSTR  = 36;         // QS row stride (floats): 144B, 16B-aligned rows
constexpr int GPSTR = 12;         // GP row stride (floats): 48B, 16B-aligned rows

// Dynamic smem layout (floats)
constexpr int OFF_QS   = 0;                        // [T][QSTR]  Q, later reused for P
constexpr int OFF_W1T  = OFF_QS + T * QSTR;        // [C][DC]  W1 transposed
constexpr int OFF_WPS  = OFF_W1T + C * DC;         // [C][DC]
constexpr int OFF_G    = OFF_WPS + C * DC;         // [DC][DC]
constexpr int OFF_GP   = OFF_G + DC * DC;          // [1024][GPSTR] Gram partials
constexpr int OFF_AL1  = OFF_GP + 1024 * GPSTR;
constexpr int OFF_BI1  = OFF_AL1 + DC;
constexpr int OFF_AL2  = OFF_BI1 + DC;
constexpr int OFF_BI2  = OFF_AL2 + C;
constexpr int OFF_REDM = OFF_BI2 + C;              // [DC][8]
constexpr int OFF_REDS = OFF_REDM + DC * 8;        // [DC][8]
constexpr int OFF_FINM = OFF_REDS + DC * 8;        // [DC]
constexpr int OFF_FINI = OFF_FINM + DC;            // [DC]
constexpr int SMEM_FLOATS = OFF_FINI + DC;
constexpr int SMEM_BYTES  = SMEM_FLOATS * 4;       // ~146 KB

#define DEVI __device__ __forceinline__
typedef unsigned long long ull;

// Packed fp32x2 helpers (Blackwell FFMA2 — only reachable via PTX)
DEVI ull ffma2(ull a, ull b, ull c) {
    ull d;
    asm("fma.rn.f32x2 %0, %1, %2, %3;" : "=l"(d) : "l"(a), "l"(b), "l"(c));
    return d;
}
DEVI ull pack2(float lo, float hi) {
    ull d;
    asm("mov.b64 %0, {%1, %2};" : "=l"(d) : "f"(lo), "f"(hi));
    return d;
}
DEVI void unpack2(ull v, float& lo, float& hi) {
    asm("mov.b64 {%0, %1}, %2;" : "=f"(lo), "=f"(hi) : "l"(v));
}
DEVI float hadd4(ull s0, ull s1) {
    float a, b, c, d;
    unpack2(s0, a, b);
    unpack2(s1, c, d);
    return (a + b) + (c + d);
}

__global__ __launch_bounds__(THREADS, 1) void attn_fused_kernel(
    const float* __restrict__ inp, const float* __restrict__ w1, const float* __restrict__ b1,
    const float* __restrict__ g1,  const float* __restrict__ be1, const float* __restrict__ m1,
    const float* __restrict__ v1,  const float* __restrict__ a1p,
    const float* __restrict__ wp,  const float* __restrict__ bp,
    const float* __restrict__ g2,  const float* __restrict__ be2, const float* __restrict__ m2,
    const float* __restrict__ v2,  const float* __restrict__ a2p,
    float* __restrict__ out)
{
    extern __shared__ float sm[];
    float* QS   = sm + OFF_QS;
    float* W1T  = sm + OFF_W1T;
    float* WPS  = sm + OFF_WPS;
    float* G    = sm + OFF_G;
    float* GP   = sm + OFF_GP;
    float* AL1  = sm + OFF_AL1;
    float* BI1  = sm + OFF_BI1;
    float* AL2  = sm + OFF_AL2;
    float* BI2  = sm + OFF_BI2;
    float* REDM = sm + OFF_REDM;
    float* REDS = sm + OFF_REDS;
    float* FINM = sm + OFF_FINM;
    float* FINI = sm + OFF_FINI;

    const int bf    = blockIdx.x;
    const int b     = bf >> 7;            // F = 128
    const int f     = bf & (F - 1);
    const int tid   = threadIdx.x;
    const int lane  = tid & 31;
    const int wid   = tid >> 5;           // = h*8 + slice
    const int h     = tid >> 8;           // channel quarter [0,4)
    const int t2    = tid & 255;
    const int slice = t2 >> 5;            // [0,8)
    const int c0    = 8 * h;              // conv1 / softmax channel base
    const int co0   = 16 * h;             // conv2 output base
    const int ta    = t2;
    const int tb    = t2 + 256;

    // ---- weights (conv1 transposed) / fused BN params ----
    for (int i = tid; i < C * DC; i += THREADS) {
        int ci = i >> 5, c = i & (DC - 1);     // W1T[ci][c] = w1[c][ci]
        W1T[i] = w1[c * C + ci];
        WPS[i] = wp[i];
    }
    if (tid < DC) {
        float sc = g1[tid] * rsqrtf(v1[tid] + 1e-5f);
        AL1[tid] = sc;
        BI1[tid] = (b1[tid] - m1[tid]) * sc + be1[tid];
    }
    if (tid < C) {
        float sc = g2[tid] * rsqrtf(v2[tid] + 1e-5f);
        AL2[tid] = sc;
        BI2[tid] = (bp[tid] - m2[tid]) * sc + be2[tid];
    }
    __syncthreads();

    const float pr1 = a1p[0];
    const float pr2 = a2p[0];

    // ---- phase 0: conv1 (C -> 8 channels, 2 t-columns per thread) ----
    {
        ull sa[4] = {0, 0, 0, 0}, sb[4] = {0, 0, 0, 0};
        const float* xa = inp + ((size_t)b * C * F + f) * T + ta;
        #pragma unroll 4
        for (int ci = 0; ci < C; ci++) {
            float xva = xa[(size_t)ci * F * T];
            float xvb = xa[(size_t)ci * F * T + 256];
            ull x2a = pack2(xva, xva);
            ull x2b = pack2(xvb, xvb);
            const ulonglong2* wr = (const ulonglong2*)(W1T + ci * DC + c0);
            ulonglong2 w0 = wr[0], w1v = wr[1];       // 2 broadcast LDS.128
            sa[0] = ffma2(x2a, w0.x,  sa[0]);
            sa[1] = ffma2(x2a, w0.y,  sa[1]);
            sa[2] = ffma2(x2a, w1v.x, sa[2]);
            sa[3] = ffma2(x2a, w1v.y, sa[3]);
            sb[0] = ffma2(x2b, w0.x,  sb[0]);
            sb[1] = ffma2(x2b, w0.y,  sb[1]);
            sb[2] = ffma2(x2b, w1v.x, sb[2]);
            sb[3] = ffma2(x2b, w1v.y, sb[3]);
        }
        float qa[8], qb[8];
        #pragma unroll
        for (int i = 0; i < 4; i++) {
            unpack2(sa[i], qa[2 * i], qa[2 * i + 1]);
            unpack2(sb[i], qb[2 * i], qb[2 * i + 1]);
        }
        #pragma unroll
        for (int j = 0; j < 8; j++) {
            float sc = AL1[c0 + j], bi = BI1[c0 + j];
            float za = qa[j] * sc + bi;
            float zb = qb[j] * sc + bi;
            qa[j] = (za >= 0.f) ? za : pr1 * za;
            qb[j] = (zb >= 0.f) ? zb : pr1 * zb;
        }
        *(float4*)(QS + ta * QSTR + c0)     = make_float4(qa[0], qa[1], qa[2], qa[3]);
        *(float4*)(QS + ta * QSTR + c0 + 4) = make_float4(qa[4], qa[5], qa[6], qa[7]);
        *(float4*)(QS + tb * QSTR + c0)     = make_float4(qb[0], qb[1], qb[2], qb[3]);
        *(float4*)(QS + tb * QSTR + c0 + 4) = make_float4(qb[4], qb[5], qb[6], qb[7]);
    }
    __syncthreads();

    // ---- phase 1: Gram partials. Warp (h, slice): rows c=lane, cols [c0,c0+8),
    //      over 64 t (its 32-slice in both halves). ----
    {
        ull acc[4] = {0, 0, 0, 0};
        const float* base = QS + (slice * 32) * QSTR;
        #pragma unroll 4
        for (int s = 0; s < 32; s++) {
            const float* r1 = base + s * QSTR;
            const float* r2 = r1 + 256 * QSTR;
            float q1 = r1[lane];                       // conflict-free LDS.32
            float q2v = r2[lane];
            ull p1 = pack2(q1, q1), p2 = pack2(q2v, q2v);
            ulonglong2 v10 = *(const ulonglong2*)(r1 + c0);
            ulonglong2 v11 = *(const ulonglong2*)(r1 + c0 + 4);
            ulonglong2 v20 = *(const ulonglong2*)(r2 + c0);
            ulonglong2 v21 = *(const ulonglong2*)(r2 + c0 + 4);
            acc[0] = ffma2(p1, v10.x, acc[0]);
            acc[1] = ffma2(p1, v10.y, acc[1]);
            acc[2] = ffma2(p1, v11.x, acc[2]);
            acc[3] = ffma2(p1, v11.y, acc[3]);
            acc[0] = ffma2(p2, v20.x, acc[0]);
            acc[1] = ffma2(p2, v20.y, acc[1]);
            acc[2] = ffma2(p2, v21.x, acc[2]);
            acc[3] = ffma2(p2, v21.y, acc[3]);
        }
        float* prow = GP + (wid * 32 + lane) * GPSTR;
        *(ulonglong2*)(prow)     = make_ulonglong2(acc[0], acc[1]);
        *(ulonglong2*)(prow + 4) = make_ulonglong2(acc[2], acc[3]);
    }
    __syncthreads();
    // reduce 8 slice-partials per entry: thread owns G[c][col]
    {
        const int c = tid & 31, col = tid >> 5;
        const int h2 = col >> 3, j = col & 7;
        float s = 0.f;
        #pragma unroll
        for (int w = 0; w < 8; w++)
            s += GP[((h2 * 8 + w) * 32 + c) * GPSTR + j];
        G[c * DC + col] = s * 0.17677669529663687f;    // 1/sqrt(32)
    }
    __syncthreads();

    // ---- phase 2: A[c,t] = G[c,:] . q[:,t] for 8 c x 2 t, G rows amortized ----
    float ea[8], eb[8];                                // holds aa, then exp values
    {
        float aaa[8], aab[8];
        #pragma unroll
        for (int j = 0; j < 8; j++) { aaa[j] = 0.f; aab[j] = 0.f; }
        #pragma unroll
        for (int k = 0; k < 2; k++) {                  // q chunks of 16 channels
            ull qa8[8], qb8[8];
            {
                const ulonglong2* p = (const ulonglong2*)(QS + ta * QSTR + 16 * k);
                ulonglong2 u0 = p[0], u1 = p[1], u2 = p[2], u3 = p[3];
                qa8[0] = u0.x; qa8[1] = u0.y; qa8[2] = u1.x; qa8[3] = u1.y;
                qa8[4] = u2.x; qa8[5] = u2.y; qa8[6] = u3.x; qa8[7] = u3.y;
            }
            {
                const ulonglong2* p = (const ulonglong2*)(QS + tb * QSTR + 16 * k);
                ulonglong2 u0 = p[0], u1 = p[1], u2 = p[2], u3 = p[3];
                qb8[0] = u0.x; qb8[1] = u0.y; qb8[2] = u1.x; qb8[3] = u1.y;
                qb8[4] = u2.x; qb8[5] = u2.y; qb8[6] = u3.x; qb8[7] = u3.y;
            }
            #pragma unroll
            for (int j = 0; j < 8; j++) {
                const ulonglong2* gr = (const ulonglong2*)(G + (c0 + j) * DC + 16 * k);
                ulonglong2 g0 = gr[0], g1v = gr[1], g2v = gr[2], g3 = gr[3];
                ull s0, s1;
                s0 = ffma2(qa8[0], g0.x,  0ULL);
                s1 = ffma2(qa8[1], g0.y,  0ULL);
                s0 = ffma2(qa8[2], g1v.x, s0);
                s1 = ffma2(qa8[3], g1v.y, s1);
                s0 = ffma2(qa8[4], g2v.x, s0);
                s1 = ffma2(qa8[5], g2v.y, s1);
                s0 = ffma2(qa8[6], g3.x,  s0);
                s1 = ffma2(qa8[7], g3.y,  s1);
                aaa[j] += hadd4(s0, s1);
                s0 = ffma2(qb8[0], g0.x,  0ULL);
                s1 = ffma2(qb8[1], g0.y,  0ULL);
                s0 = ffma2(qb8[2], g1v.x, s0);
                s1 = ffma2(qb8[3], g1v.y, s1);
                s0 = ffma2(qb8[4], g2v.x, s0);
                s1 = ffma2(qb8[5], g2v.y, s1);
                s0 = ffma2(qb8[6], g3.x,  s0);
                s1 = ffma2(qb8[7], g3.y,  s1);
                aab[j] += hadd4(s0, s1);
            }
        }
        // mask: t_a < 256 is never masked; t_b masked iff t2 >= f + 129
        if (t2 >= f + (T - F + 1) - 256) {
            #pragma unroll
            for (int j = 0; j < 8; j++) aab[j] = -FLT_MAX;
        }

        // ---- phase 3 stage A: warp softmax partials over 64 t per warp ----
        #pragma unroll
        for (int j = 0; j < 8; j++) {
            float m = fmaxf(aaa[j], aab[j]);
            #pragma unroll
            for (int o = 16; o > 0; o >>= 1)
                m = fmaxf(m, __shfl_xor_sync(0xffffffffu, m, o));
            float va = __expf(aaa[j] - m);
            float vb = __expf(aab[j] - m);
            float s = va + vb;
            #pragma unroll
            for (int o = 16; o > 0; o >>= 1)
                s += __shfl_xor_sync(0xffffffffu, s, o);
            if (lane == 0) {
                REDM[(c0 + j) * 8 + slice] = m;
                REDS[(c0 + j) * 8 + slice] = s;
            }
            ea[j] = va;
            eb[j] = vb;
        }
    }
    __syncthreads();
    // stage B: combine 8 warp partials per channel
    if (tid < DC) {
        float M = -FLT_MAX;
        #pragma unroll
        for (int w = 0; w < 8; w++) M = fmaxf(M, REDM[tid * 8 + w]);
        float S = 0.f;
        #pragma unroll
        for (int w = 0; w < 8; w++) S += REDS[tid * 8 + w] * __expf(REDM[tid * 8 + w] - M);
        FINM[tid] = M;
        FINI[tid] = 1.f / S;
    }
    __syncthreads();
    // stage C: finalize probabilities, store into QS (Q no longer needed)
    {
        float pa[8], pb[8];
        #pragma unroll
        for (int j = 0; j < 8; j++) {
            int c = c0 + j;
            float fac = __expf(REDM[c * 8 + slice] - FINM[c]) * FINI[c];
            pa[j] = ea[j] * fac;
            pb[j] = eb[j] * fac;
        }
        *(float4*)(QS + ta * QSTR + c0)     = make_float4(pa[0], pa[1], pa[2], pa[3]);
        *(float4*)(QS + ta * QSTR + c0 + 4) = make_float4(pa[4], pa[5], pa[6], pa[7]);
        *(float4*)(QS + tb * QSTR + c0)     = make_float4(pb[0], pb[1], pb[2], pb[3]);
        *(float4*)(QS + tb * QSTR + c0 + 4) = make_float4(pb[4], pb[5], pb[6], pb[7]);
    }
    __syncthreads();

    // ---- phase 4: conv2 (32 -> 16 outputs, 2 t-columns), W rows amortized ----
    const size_t obase = ((size_t)b * C * F + f) * T;
    #pragma unroll
    for (int g = 0; g < 2; g++) {
        float acca[8], accb[8];
        #pragma unroll
        for (int i = 0; i < 8; i++) { acca[i] = 0.f; accb[i] = 0.f; }
        #pragma unroll
        for (int k = 0; k < 2; k++) {
            ull Pa[8], Pb[8];
            {
                const ulonglong2* p = (const ulonglong2*)(QS + ta * QSTR + 16 * k);
                ulonglong2 u0 = p[0], u1 = p[1], u2 = p[2], u3 = p[3];
                Pa[0] = u0.x; Pa[1] = u0.y; Pa[2] = u1.x; Pa[3] = u1.y;
                Pa[4] = u2.x; Pa[5] = u2.y; Pa[6] = u3.x; Pa[7] = u3.y;
            }
            {
                const ulonglong2* p = (const ulonglong2*)(QS + tb * QSTR + 16 * k);
                ulonglong2 u0 = p[0], u1 = p[1], u2 = p[2], u3 = p[3];
                Pb[0] = u0.x; Pb[1] = u0.y; Pb[2] = u1.x; Pb[3] = u1.y;
                Pb[4] = u2.x; Pb[5] = u2.y; Pb[6] = u3.x; Pb[7] = u3.y;
            }
            #pragma unroll
            for (int i = 0; i < 8; i++) {
                int co = co0 + 8 * g + i;
                const ulonglong2* wr = (const ulonglong2*)(WPS + co * DC + 16 * k);
                ulonglong2 w0 = wr[0], w1v = wr[1], w2v = wr[2], w3 = wr[3];
                ull s0, s1;
                s0 = ffma2(Pa[0], w0.x,  0ULL);
                s1 = ffma2(Pa[1], w0.y,  0ULL);
                s0 = ffma2(Pa[2], w1v.x, s0);
                s1 = ffma2(Pa[3], w1v.y, s1);
                s0 = ffma2(Pa[4], w2v.x, s0);
                s1 = ffma2(Pa[5], w2v.y, s1);
                s0 = ffma2(Pa[6], w3.x,  s0);
                s1 = ffma2(Pa[7], w3.y,  s1);
                acca[i] += hadd4(s0, s1);
                s0 = ffma2(Pb[0], w0.x,  0ULL);
                s1 = ffma2(Pb[1], w0.y,  0ULL);
                s0 = ffma2(Pb[2], w1v.x, s0);
                s1 = ffma2(Pb[3], w1v.y, s1);
                s0 = ffma2(Pb[4], w2v.x, s0);
                s1 = ffma2(Pb[5], w2v.y, s1);
                s0 = ffma2(Pb[6], w3.x,  s0);
                s1 = ffma2(Pb[7], w3.y,  s1);
                accb[i] += hadd4(s0, s1);
            }
        }
        #pragma unroll
        for (int i = 0; i < 8; i++) {
            int co = co0 + 8 * g + i;
            float sc = AL2[co], bi = BI2[co];
            float za = acca[i] * sc + bi;
            float zb = accb[i] * sc + bi;
            za = (za >= 0.f) ? za : pr2 * za;
            zb = (zb >= 0.f) ? zb : pr2 * zb;
            size_t ia = obase + (size_t)co * F * T + ta;
            out[ia]       = za + inp[ia];
            out[ia + 256] = zb + inp[ia + 256];
        }
    }
}

extern "C" void kernel_launch(void* const* d_in, const int* in_sizes, int n_in,
                              void* d_out, int out_size) {
    const float* inp = (const float*)d_in[0];
    const float* w1  = (const float*)d_in[1];
    const float* b1  = (const float*)d_in[2];
    const float* g1  = (const float*)d_in[3];
    const float* be1 = (const float*)d_in[4];
    const float* m1  = (const float*)d_in[5];
    const float* v1  = (const float*)d_in[6];
    const float* a1  = (const float*)d_in[7];
    const float* wp  = (const float*)d_in[8];
    const float* bp  = (const float*)d_in[9];
    const float* g2  = (const float*)d_in[10];
    const float* be2 = (const float*)d_in[11];
    const float* m2  = (const float*)d_in[12];
    const float* v2  = (const float*)d_in[13];
    const float* a2  = (const float*)d_in[14];
    float* out = (float*)d_out;

    cudaFuncSetAttribute(attn_fused_kernel,
                         cudaFuncAttributeMaxDynamicSharedMemorySize, SMEM_BYTES);
    attn_fused_kernel<<<B * F, THREADS, SMEM_BYTES>>>(
        inp, w1, b1, g1, be1, m1, v1, a1, wp, bp, g2, be2, m2, v2, a2, out);
}